// round 15
// baseline (speedup 1.0000x reference)
#include <cuda_runtime.h>
#include <cuda_bf16.h>
#include <cstdint>
#include <math.h>

#define S_  4
#define L_  3
#define D_  256
#define DI_ 512
#define N_  16
#define KC_ 4
#define R_  16
#define IN_ 32
#define E_  128
#define B_  8
#define T_  512
#define ROWS  (B_*T_)      // 4096 rows per stream
#define TROWS (S_*ROWS)    // 16384 total rows

typedef __nv_bfloat16 bf16;

// ---------------- scratch (device globals; no runtime allocation) ------------
__device__ float g_h   [S_*ROWS*D_];
__device__ float g_xz  [S_*ROWS*2*DI_];     // xi = [:,0:512], z = [:,512:1024]
__device__ float g_u   [S_*ROWS*DI_];
__device__ float g_xdbl[S_*ROWS*48];        // dt_in[0:16], B[16:32], C[32:48]
__device__ float g_hpart[S_*B_*8*D_];

__device__ bf16 g_h_bf [S_*ROWS*D_];
__device__ bf16 g_u_bf [S_*ROWS*DI_];
__device__ bf16 g_y_bf [S_*ROWS*DI_];

__device__ bf16 g_inw_bf [S_*L_*2*DI_*D_];
__device__ bf16 g_outw_bf[S_*L_*D_*DI_];
__device__ bf16 g_xpw_bf [S_*L_*64*DI_];    // padded 48 -> 64 rows

// ---------------- helpers ----------------------------------------------------
__device__ __forceinline__ float softplus_f(float x) {
    float e = __expf(x);
    return (x > 20.f) ? x : __logf(1.f + e);
}
__device__ __forceinline__ float silu_f(float x) {
    return x / (1.f + __expf(-x));
}
__device__ __forceinline__ uint32_t smem_u32(const void* p) {
    uint32_t a;
    asm("{ .reg .u64 t; cvta.to.shared.u64 t, %1; cvt.u32.u64 %0, t; }" : "=r"(a) : "l"(p));
    return a;
}
__device__ __forceinline__ void cp16(uint32_t dst, const void* src) {
    asm volatile("cp.async.cg.shared.global [%0], [%1], 16;" :: "r"(dst), "l"(src));
}
#define CP_COMMIT() asm volatile("cp.async.commit_group;")
#define CP_WAIT0()  asm volatile("cp.async.wait_group 0;")
#define CP_WAIT1()  asm volatile("cp.async.wait_group 1;")

__device__ __forceinline__ void mma_bf16(float* c, const uint32_t* a, const uint32_t* b) {
    asm volatile(
        "mma.sync.aligned.m16n8k16.row.col.f32.bf16.bf16.f32 "
        "{%0,%1,%2,%3}, {%4,%5,%6,%7}, {%8,%9}, {%0,%1,%2,%3};"
        : "+f"(c[0]), "+f"(c[1]), "+f"(c[2]), "+f"(c[3])
        : "r"(a[0]), "r"(a[1]), "r"(a[2]), "r"(a[3]), "r"(b[0]), "r"(b[1]));
}
__device__ __forceinline__ void ldsm_x4(uint32_t* r, uint32_t addr) {
    asm volatile("ldmatrix.sync.aligned.m8n8.x4.shared.b16 {%0,%1,%2,%3}, [%4];"
        : "=r"(r[0]), "=r"(r[1]), "=r"(r[2]), "=r"(r[3]) : "r"(addr));
}

// ---------------- weight conversion ------------------------------------------
__global__ void convert_bf_kernel(const float* __restrict__ src,
                                  bf16* __restrict__ dst, int n)
{
    int i = blockIdx.x * blockDim.x + threadIdx.x;
    if (i < n) dst[i] = __float2bfloat16(src[i]);
}

__global__ void convert_xpw_kernel(const float* __restrict__ src)  // [S*L][48][512] -> padded 64
{
    int i = blockIdx.x * blockDim.x + threadIdx.x;
    int n = S_ * L_ * 64 * DI_;
    if (i >= n) return;
    int k = i % DI_;
    int row = (i / DI_) % 64;
    int sl = i / (64 * DI_);
    float v = (row < 48) ? src[((long)sl * 48 + row) * DI_ + k] : 0.f;
    g_xpw_bf[i] = __float2bfloat16(v);
}

// ---------------- input projection (SMEM-staged): h = x @ ipw^T + ipb ---------
__global__ void __launch_bounds__(256) input_proj_kernel(
    const float* __restrict__ t0, const float* __restrict__ t1,
    const float* __restrict__ t2, const float* __restrict__ t3,
    const float* __restrict__ ipw, const float* __restrict__ ipb)
{
    __shared__ float Ws[D_][IN_ + 1];
    __shared__ float xs[32][IN_ + 1];

    int blk = blockIdx.x;                 // 0..511
    int s   = blk >> 7;
    int bt0 = (blk * 32) & 4095;
    const float* x = (s == 0) ? t0 : (s == 1) ? t1 : (s == 2) ? t2 : t3;

    const float* wsrc = ipw + (long)s * D_ * IN_;
    for (int i = threadIdx.x; i < D_ * IN_; i += 256)
        Ws[i >> 5][i & 31] = wsrc[i];
    const float* xsrc = x + (long)bt0 * IN_;
    for (int i = threadIdx.x; i < 32 * IN_; i += 256)
        xs[i >> 5][i & 31] = xsrc[i];
    __syncthreads();

    int d = threadIdx.x;
    float w[IN_];
#pragma unroll
    for (int k = 0; k < IN_; ++k) w[k] = Ws[d][k];
    float bias = ipb[s * D_ + d];

    long gbase = (long)blk * 32 * D_ + d;
#pragma unroll 4
    for (int r = 0; r < 32; ++r) {
        float acc = bias;
#pragma unroll
        for (int k = 0; k < IN_; ++k) acc = fmaf(xs[r][k], w[k], acc);
        long o = gbase + (long)r * D_;
        g_h[o] = acc;
        g_h_bf[o] = __float2bfloat16(acc);
    }
}

// ---------------- HMMA bf16 GEMM (single term, templated BN) ------------------
// C[M,N] = A[M,K] * W[N,K]^T, bf16 inputs, fp32 accum.
// CTA tile 128xBN x32, 8 warps (4M x 2N), warp tile 32x(BN/2), mma m16n8k16.
#define RPAD 80            // bytes per SMEM row (40 bf16)

template<int BN>
__global__ void __launch_bounds__(256) gemm_tc_kernel(
    const bf16* __restrict__ Abf, long aStride,
    const bf16* __restrict__ Wbf, long wStride,
    float* __restrict__ C, int ldc, long cStride,
    bf16* __restrict__ Cbf,
    int K, int nValid)
{
    constexpr int NI    = BN / 16;                // per-warp 8-col tiles
    constexpr int STG_B = (128 + BN) * RPAD;      // bytes per stage
    constexpr int W_OFF = 128 * RPAD;
    constexpr int NCP   = (128 + BN) * 4;         // cp16 ops per stage

    extern __shared__ char smem[];
    uint32_t sb = smem_u32(smem);
    int tid = threadIdx.x;
    int wid = tid >> 5, lid = tid & 31;
    int warp_m = wid & 3, warp_n = wid >> 2;
    int gid = lid >> 2, ktid = lid & 3;
    int s = blockIdx.z;
    long bm = (long)blockIdx.y * 128;
    long bn = (long)blockIdx.x * BN;

    const bf16* A = Abf + s * aStride;
    const bf16* W = Wbf + s * wStride;

    float acc[2][NI][4];
#pragma unroll
    for (int mi = 0; mi < 2; ++mi)
#pragma unroll
        for (int ni = 0; ni < NI; ++ni)
#pragma unroll
            for (int q = 0; q < 4; ++q) acc[mi][ni][q] = 0.f;

    auto load_stage = [&](int stg, int k0) {
        uint32_t base = sb + stg * STG_B;
#pragma unroll
        for (int i = tid; i < NCP; i += 256) {
            const bf16* src; uint32_t doff;
            if (i < 512) {
                int r = i >> 2, c = i & 3;
                src  = A + (bm + r) * K + k0 + c * 8;
                doff = base + r * RPAD + c * 16;
            } else {
                int j = i - 512, r = j >> 2, c = j & 3;
                src  = W + (bn + r) * K + k0 + c * 8;
                doff = base + W_OFF + r * RPAD + c * 16;
            }
            cp16(doff, src);
        }
    };

    int nst = K >> 5;
    load_stage(0, 0);
    CP_COMMIT();

    uint32_t aoff = (uint32_t)(warp_m * 32 + (lid & 7) + ((lid >> 3) & 1) * 8) * RPAD
                  + ((lid >> 4) & 1) * 16;
    uint32_t boff = (uint32_t)(warp_n * (BN / 2) + ((lid >> 4) & 1) * 8 + (lid & 7)) * RPAD
                  + ((lid >> 3) & 1) * 16;

    for (int st = 0; st < nst; ++st) {
        if (st + 1 < nst) {
            load_stage((st + 1) & 1, (st + 1) << 5);
            CP_COMMIT();
            CP_WAIT1();
        } else {
            CP_WAIT0();
        }
        __syncthreads();

        uint32_t stg = sb + (st & 1) * STG_B;

#pragma unroll
        for (int kc = 0; kc < 2; ++kc) {
            int kb = kc * 32;
            uint32_t ah[2][4], bh[NI][2], t4[4];
#pragma unroll
            for (int mi = 0; mi < 2; ++mi)
                ldsm_x4(ah[mi], stg + aoff + mi * 16 * RPAD + kb);
#pragma unroll
            for (int pr = 0; pr < NI / 2; ++pr) {
                ldsm_x4(t4, stg + W_OFF + boff + pr * 16 * RPAD + kb);
                bh[2 * pr][0] = t4[0]; bh[2 * pr][1] = t4[1];
                bh[2 * pr + 1][0] = t4[2]; bh[2 * pr + 1][1] = t4[3];
            }
#pragma unroll
            for (int mi = 0; mi < 2; ++mi)
#pragma unroll
                for (int ni = 0; ni < NI; ++ni)
                    mma_bf16(acc[mi][ni], ah[mi], bh[ni]);
        }
        __syncthreads();
    }

#pragma unroll
    for (int mi = 0; mi < 2; ++mi) {
        long row = bm + warp_m * 32 + mi * 16 + gid;
#pragma unroll
        for (int ni = 0; ni < NI; ++ni) {
            int cl = warp_n * (BN / 2) + ni * 8 + ktid * 2;
            if (cl >= nValid) continue;
            float* c0 = C + s * cStride + row * ldc + bn + cl;
            float* c1 = C + s * cStride + (row + 8) * ldc + bn + cl;
            *(float2*)c0 = make_float2(acc[mi][ni][0], acc[mi][ni][1]);
            *(float2*)c1 = make_float2(acc[mi][ni][2], acc[mi][ni][3]);
            if (Cbf) {
                __nv_bfloat162 hv;
                hv.x = __float2bfloat16(acc[mi][ni][0]);
                hv.y = __float2bfloat16(acc[mi][ni][1]);
                *(__nv_bfloat162*)(Cbf + s * cStride + row * ldc + bn + cl) = hv;
                hv.x = __float2bfloat16(acc[mi][ni][2]);
                hv.y = __float2bfloat16(acc[mi][ni][3]);
                *(__nv_bfloat162*)(Cbf + s * cStride + (row + 8) * ldc + bn + cl) = hv;
            }
        }
    }
}

#define GSM_128 (2 * (128 + 128) * RPAD)   // 40960
#define GSM_64  (2 * (128 + 64) * RPAD)    // 30720

// ---------------- depthwise causal conv (K=4) + bias + silu -------------------
__global__ void __launch_bounds__(128) conv_silu_kernel(
    const float* __restrict__ cw, const float* __restrict__ cb, int l)
{
    int zidx = blockIdx.z;                // 0..31  (s*8+b)
    int s = zidx >> 3, b = zidx & 7;
    int c = blockIdx.y;                   // 0..7 t-chunk
    int t0 = c * 64;
    int d = blockIdx.x * 128 + threadIdx.x;
    int sl = s * L_ + l;

    const float* w = cw + ((long)sl * DI_ + d) * KC_;
    float w0 = w[0], w1 = w[1], w2 = w[2], w3 = w[3];
    float bias = cb[sl * DI_ + d];

    long rowbase = (long)s * ROWS + (long)b * T_;
    const float* xi = g_xz + (rowbase + t0) * 2 * DI_ + d;
    long ub = (rowbase + t0) * DI_ + d;

    float x0, x1, x2;
    if (t0) {
        x0 = xi[-3 * 2 * DI_]; x1 = xi[-2 * 2 * DI_]; x2 = xi[-1 * 2 * DI_];
    } else {
        x0 = x1 = x2 = 0.f;
    }
#pragma unroll 4
    for (int tt = 0; tt < 64; ++tt) {
        float x3 = xi[(long)tt * 2 * DI_];
        float a = fmaf(w0, x0, fmaf(w1, x1, fmaf(w2, x2, fmaf(w3, x3, bias))));
        float uv = silu_f(a);
        long o = ub + (long)tt * DI_;
        g_u[o] = uv;
        g_u_bf[o] = __float2bfloat16(uv);
        x0 = x1; x1 = x2; x2 = x3;
    }
}

// ---------------- fused dt + SSM scan + skip + gate ---------------------------
// 2 threads per channel: n-state split 8/8 across lane pairs; y via shfl_xor.
#define SCH 16
__global__ void __launch_bounds__(128) scan_kernel(
    const float* __restrict__ dtw, const float* __restrict__ dtb,
    const float* __restrict__ alog, const float* __restrict__ dpar, int l)
{
    __shared__ float s_xd[SCH * 48];
    __shared__ float s_u[SCH][64];
    __shared__ float s_z[SCH][64];

    int s = blockIdx.z, b = blockIdx.y;
    int tid = threadIdx.x;
    int ch = tid >> 1;                  // 0..63 channel within block
    int half = tid & 1;                 // n-half: 0 -> n 0..7, 1 -> n 8..15
    int d = blockIdx.x * 64 + ch;
    int sl = s * L_ + l;
    int nb = half * 8;

    const float* ap = alog + ((long)sl * DI_ + d) * N_;
    float A0 = -__expf(ap[0]);
    float A[8];
#pragma unroll
    for (int n = 0; n < 8; ++n) A[n] = -__expf(ap[nb + n]);
    bool geo = true;
#pragma unroll
    for (int n = 0; n < 8; ++n)
        geo = geo && (fabsf(A[n] - (float)(nb + n + 1) * A0)
                      <= 1e-4f * fabsf(A[n]) + 1e-6f);

    float wdt[R_];
    const float* wp = dtw + ((long)sl * DI_ + d) * R_;
#pragma unroll
    for (int r = 0; r < R_; ++r) wdt[r] = wp[r];

    float dtbias = dtb[sl * DI_ + d];
    float Dp     = dpar[sl * DI_ + d];

    long rowbase = (long)s * ROWS + (long)b * T_;
    const float* upb = g_u  + rowbase * DI_ + blockIdx.x * 64;
    const float* zpb = g_xz + rowbase * 2 * DI_ + DI_ + blockIdx.x * 64;
    const float* xd  = g_xdbl + rowbase * 48;
    long yb = rowbase * DI_ + d;

    float h[8];
#pragma unroll
    for (int n = 0; n < 8; ++n) h[n] = 0.f;

    for (int t0 = 0; t0 < T_; t0 += SCH) {
        __syncthreads();
        const float4* src = (const float4*)(xd + (long)t0 * 48);
        for (int i = tid; i < SCH * 12; i += 128)
            ((float4*)s_xd)[i] = src[i];
        for (int i = tid; i < SCH * 64; i += 128) {
            int tt = i >> 6, c = i & 63;
            s_u[tt][c] = upb[(long)(t0 + tt) * DI_ + c];
            s_z[tt][c] = zpb[(long)(t0 + tt) * 2 * DI_ + c];
        }
        __syncthreads();

#pragma unroll 2
        for (int tt = 0; tt < SCH; ++tt) {
            const float* row = s_xd + tt * 48;
            // dt dot (duplicated across the pair): 4 independent chains
            float4 q0 = ((const float4*)row)[0];
            float4 q1 = ((const float4*)row)[1];
            float4 q2 = ((const float4*)row)[2];
            float4 q3 = ((const float4*)row)[3];
            float a0 = fmaf(q0.x, wdt[0], dtbias);
            float a1 = fmaf(q1.x, wdt[4], 0.f);
            float a2 = fmaf(q2.x, wdt[8], 0.f);
            float a3 = fmaf(q3.x, wdt[12], 0.f);
            a0 = fmaf(q0.y, wdt[1], a0); a1 = fmaf(q1.y, wdt[5], a1);
            a2 = fmaf(q2.y, wdt[9], a2); a3 = fmaf(q3.y, wdt[13], a3);
            a0 = fmaf(q0.z, wdt[2], a0); a1 = fmaf(q1.z, wdt[6], a1);
            a2 = fmaf(q2.z, wdt[10], a2); a3 = fmaf(q3.z, wdt[14], a3);
            a0 = fmaf(q0.w, wdt[3], a0); a1 = fmaf(q1.w, wdt[7], a1);
            a2 = fmaf(q2.w, wdt[11], a2); a3 = fmaf(q3.w, wdt[15], a3);
            float dt = softplus_f((a0 + a1) + (a2 + a3));

            // this half's B and C slices
            float4 b0 = ((const float4*)(row + 16 + nb))[0];
            float4 b1 = ((const float4*)(row + 16 + nb))[1];
            float4 c0 = ((const float4*)(row + 32 + nb))[0];
            float4 c1 = ((const float4*)(row + 32 + nb))[1];
            float xb[8] = {b0.x, b0.y, b0.z, b0.w, b1.x, b1.y, b1.z, b1.w};
            float xc[8] = {c0.x, c0.y, c0.z, c0.w, c1.x, c1.y, c1.z, c1.w};

            float u = s_u[tt][ch];
            float z = s_z[tt][ch];
            float du = dt * u;

            if (geo) {
                float p = __expf(dt * A0);
                float p2 = p * p, p3 = p2 * p, p4 = p2 * p2;
                float p5 = p4 * p, p6 = p4 * p2, p7 = p4 * p3, p8 = p4 * p4;
                float sc = half ? p8 : 1.f;
                float pw[8] = {p * sc, p2 * sc, p3 * sc, p4 * sc,
                               p5 * sc, p6 * sc, p7 * sc, p8 * sc};
#pragma unroll
                for (int n = 0; n < 8; ++n)
                    h[n] = fmaf(pw[n], h[n], du * xb[n]);
            } else {
#pragma unroll
                for (int n = 0; n < 8; ++n)
                    h[n] = fmaf(__expf(dt * A[n]), h[n], du * xb[n]);
            }

            float y0 = 0.f, y1 = 0.f, y2 = 0.f, y3 = 0.f;
#pragma unroll
            for (int n = 0; n < 8; n += 4) {
                y0 = fmaf(h[n],     xc[n],     y0);
                y1 = fmaf(h[n + 1], xc[n + 1], y1);
                y2 = fmaf(h[n + 2], xc[n + 2], y2);
                y3 = fmaf(h[n + 3], xc[n + 3], y3);
            }
            float yp = (y0 + y1) + (y2 + y3);
            yp += __shfl_xor_sync(0xffffffffu, yp, 1);
            if (!half) {
                float y = (yp + u * Dp) * silu_f(z);
                g_y_bf[yb + (long)(t0 + tt) * DI_] = __float2bfloat16(y);
            }
        }
    }
}

// ---------------- mean over t (two-stage) + output projection -----------------
__global__ void __launch_bounds__(256) mean_part_kernel()
{
    int c = blockIdx.x, b = blockIdx.y, s = blockIdx.z;
    int d = threadIdx.x;
    const float* hp = g_h + ((long)s * ROWS + (long)b * T_ + (long)c * 64) * D_ + d;
    float acc = 0.f;
#pragma unroll 8
    for (int t = 0; t < 64; ++t) acc += hp[(long)t * D_];
    g_hpart[(((long)s * B_ + b) * 8 + c) * D_ + d] = acc;
}

__global__ void __launch_bounds__(256) meanout_kernel(
    const float* __restrict__ opw, const float* __restrict__ opb, float* __restrict__ out)
{
    int b = blockIdx.x, s = blockIdx.y;
    __shared__ float hm[D_];
    int d = threadIdx.x;
    const float* pp = g_hpart + ((long)s * B_ + b) * 8 * D_ + d;
    float acc = 0.f;
#pragma unroll
    for (int c = 0; c < 8; ++c) acc += pp[(long)c * D_];
    hm[d] = acc * (1.f / T_);
    __syncthreads();

    if (d < E_) {
        const float* w = opw + ((long)s * E_ + d) * D_;
        float e = opb[s * E_ + d];
#pragma unroll 8
        for (int k = 0; k < D_; ++k) e = fmaf(hm[k], w[k], e);
        out[((long)s * B_ + b) * E_ + d] = e;
    }
}

__global__ void combine_kernel(float* __restrict__ out)
{
    int i = blockIdx.x * blockDim.x + threadIdx.x;
    if (i < B_ * E_)
        out[4 * B_ * E_ + i] = out[i] + out[B_ * E_ + i] + out[2 * B_ * E_ + i] + out[3 * B_ * E_ + i];
}

// ---------------- launcher ----------------------------------------------------
extern "C" void kernel_launch(void* const* d_in, const int* in_sizes, int n_in,
                              void* d_out, int out_size)
{
    const float* trend    = (const float*)d_in[0];
    const float* daily    = (const float*)d_in[1];
    const float* weekly   = (const float*)d_in[2];
    const float* residual = (const float*)d_in[3];
    const float* in_proj_w  = (const float*)d_in[4];
    const float* conv_w     = (const float*)d_in[5];
    const float* conv_b     = (const float*)d_in[6];
    const float* x_proj_w   = (const float*)d_in[7];
    const float* dt_proj_w  = (const float*)d_in[8];
    const float* dt_proj_b  = (const float*)d_in[9];
    const float* A_log      = (const float*)d_in[10];
    const float* D_param    = (const float*)d_in[11];
    const float* out_proj_w = (const float*)d_in[12];
    const float* input_proj_w  = (const float*)d_in[13];
    const float* input_proj_b  = (const float*)d_in[14];
    const float* output_proj_w = (const float*)d_in[15];
    const float* output_proj_b = (const float*)d_in[16];
    float* out = (float*)d_out;

    cudaFuncSetAttribute(gemm_tc_kernel<128>,
                         cudaFuncAttributeMaxDynamicSharedMemorySize, GSM_128);
    cudaFuncSetAttribute(gemm_tc_kernel<64>,
                         cudaFuncAttributeMaxDynamicSharedMemorySize, GSM_64);

    bf16 *inw_bf, *outw_bf, *xpw_bf, *h_bf, *u_bf, *y_bf;
    float *xz, *xdbl, *hbuf;
    cudaGetSymbolAddress((void**)&inw_bf,  g_inw_bf);
    cudaGetSymbolAddress((void**)&outw_bf, g_outw_bf);
    cudaGetSymbolAddress((void**)&xpw_bf,  g_xpw_bf);
    cudaGetSymbolAddress((void**)&h_bf,    g_h_bf);
    cudaGetSymbolAddress((void**)&u_bf,    g_u_bf);
    cudaGetSymbolAddress((void**)&y_bf,    g_y_bf);
    cudaGetSymbolAddress((void**)&xz,      g_xz);
    cudaGetSymbolAddress((void**)&xdbl,    g_xdbl);
    cudaGetSymbolAddress((void**)&hbuf,    g_h);

    // Launch order keeps the big in_proj GEMM at stream-launch index 3
    // (the launch ncu captures) for a clean A/B against R14.
    {
        int n1 = S_ * L_ * 2 * DI_ * D_;                               // (0)
        convert_bf_kernel<<<(n1 + 255) / 256, 256>>>(in_proj_w, inw_bf, n1);
    }
    input_proj_kernel<<<TROWS / 32, 256>>>(trend, daily, weekly, residual,
                                           input_proj_w, input_proj_b);  // (1)
    {
        int n2 = S_ * L_ * D_ * DI_;                                   // (2)
        convert_bf_kernel<<<(n2 + 255) / 256, 256>>>(out_proj_w, outw_bf, n2);
    }

    bool xpw_converted = false;
    for (int l = 0; l < L_; ++l) {
        {
            dim3 g(2 * DI_ / 128, 32, S_);                             // (3) <- profiled
            gemm_tc_kernel<128><<<g, 256, GSM_128>>>(
                h_bf, (long)ROWS * D_,
                inw_bf + (long)l * 2 * DI_ * D_, (long)L_ * 2 * DI_ * D_,
                xz, 2 * DI_, (long)ROWS * 2 * DI_,
                nullptr, D_, 128);
        }
        if (!xpw_converted) {
            int n3 = S_ * L_ * 64 * DI_;                               // (4)
            convert_xpw_kernel<<<(n3 + 255) / 256, 256>>>(x_proj_w);
            xpw_converted = true;
        }
        {
            dim3 g(DI_ / 128, 8, 32);                                  // t-parallel conv
            conv_silu_kernel<<<g, 128>>>(conv_w, conv_b, l);
        }
        {
            dim3 g(1, 32, S_);
            gemm_tc_kernel<64><<<g, 256, GSM_64>>>(
                u_bf, (long)ROWS * DI_,
                xpw_bf + (long)l * 64 * DI_, (long)L_ * 64 * DI_,
                xdbl, 48, (long)ROWS * 48,
                nullptr, DI_, 48);
        }
        {
            dim3 g(DI_ / 64, B_, S_);
            scan_kernel<<<g, 128>>>(dt_proj_w, dt_proj_b, A_log, D_param, l);
        }
        {
            dim3 g(D_ / 128, 32, S_);
            gemm_tc_kernel<128><<<g, 256, GSM_128>>>(
                y_bf, (long)ROWS * DI_,
                outw_bf + (long)l * D_ * DI_, (long)L_ * D_ * DI_,
                hbuf, D_, (long)ROWS * D_,
                h_bf, DI_, 128);
        }
    }

    {
        dim3 gp(8, B_, S_);
        mean_part_kernel<<<gp, 256>>>();
    }
    dim3 g_mo(B_, S_);
    meanout_kernel<<<g_mo, 256>>>(output_proj_w, output_proj_b, out);
    combine_kernel<<<4, 256>>>(out);
}

// round 16
// speedup vs baseline: 1.1771x; 1.1771x over previous
#include <cuda_runtime.h>
#include <cuda_bf16.h>
#include <cstdint>
#include <math.h>

#define S_  4
#define L_  3
#define D_  256
#define DI_ 512
#define N_  16
#define KC_ 4
#define R_  16
#define IN_ 32
#define E_  128
#define B_  8
#define T_  512
#define ROWS  (B_*T_)      // 4096 rows per stream
#define TROWS (S_*ROWS)    // 16384 total rows

typedef __nv_bfloat16 bf16;

// ---------------- scratch (device globals; no runtime allocation) ------------
__device__ float g_h   [S_*ROWS*D_];
__device__ float g_xz  [S_*ROWS*2*DI_];     // xi = [:,0:512], z = [:,512:1024]
__device__ float g_u   [S_*ROWS*DI_];
__device__ float g_xdbl[S_*ROWS*48];        // dt_in[0:16], B[16:32], C[32:48]
__device__ float g_hpart[S_*B_*8*D_];

__device__ bf16 g_h_bf [S_*ROWS*D_];
__device__ bf16 g_u_bf [S_*ROWS*DI_];
__device__ bf16 g_y_bf [S_*ROWS*DI_];

__device__ bf16 g_inw_bf [S_*L_*2*DI_*D_];
__device__ bf16 g_outw_bf[S_*L_*D_*DI_];
__device__ bf16 g_xpw_bf [S_*L_*64*DI_];    // padded 48 -> 64 rows

// ---------------- helpers ----------------------------------------------------
__device__ __forceinline__ float softplus_f(float x) {
    float e = __expf(x);
    return (x > 20.f) ? x : __logf(1.f + e);
}
__device__ __forceinline__ float silu_f(float x) {
    return x / (1.f + __expf(-x));
}
__device__ __forceinline__ uint32_t smem_u32(const void* p) {
    uint32_t a;
    asm("{ .reg .u64 t; cvta.to.shared.u64 t, %1; cvt.u32.u64 %0, t; }" : "=r"(a) : "l"(p));
    return a;
}
__device__ __forceinline__ void cp16(uint32_t dst, const void* src) {
    asm volatile("cp.async.cg.shared.global [%0], [%1], 16;" :: "r"(dst), "l"(src));
}
#define CP_COMMIT() asm volatile("cp.async.commit_group;")
#define CP_WAIT0()  asm volatile("cp.async.wait_group 0;")
#define CP_WAIT1()  asm volatile("cp.async.wait_group 1;")

__device__ __forceinline__ void mma_bf16(float* c, const uint32_t* a, const uint32_t* b) {
    asm volatile(
        "mma.sync.aligned.m16n8k16.row.col.f32.bf16.bf16.f32 "
        "{%0,%1,%2,%3}, {%4,%5,%6,%7}, {%8,%9}, {%0,%1,%2,%3};"
        : "+f"(c[0]), "+f"(c[1]), "+f"(c[2]), "+f"(c[3])
        : "r"(a[0]), "r"(a[1]), "r"(a[2]), "r"(a[3]), "r"(b[0]), "r"(b[1]));
}
__device__ __forceinline__ void ldsm_x4(uint32_t* r, uint32_t addr) {
    asm volatile("ldmatrix.sync.aligned.m8n8.x4.shared.b16 {%0,%1,%2,%3}, [%4];"
        : "=r"(r[0]), "=r"(r[1]), "=r"(r[2]), "=r"(r[3]) : "r"(addr));
}

// ---------------- weight conversion ------------------------------------------
__global__ void convert_bf_kernel(const float* __restrict__ src,
                                  bf16* __restrict__ dst, int n)
{
    int i = blockIdx.x * blockDim.x + threadIdx.x;
    if (i < n) dst[i] = __float2bfloat16(src[i]);
}

__global__ void convert_xpw_kernel(const float* __restrict__ src)  // [S*L][48][512] -> padded 64
{
    int i = blockIdx.x * blockDim.x + threadIdx.x;
    int n = S_ * L_ * 64 * DI_;
    if (i >= n) return;
    int k = i % DI_;
    int row = (i / DI_) % 64;
    int sl = i / (64 * DI_);
    float v = (row < 48) ? src[((long)sl * 48 + row) * DI_ + k] : 0.f;
    g_xpw_bf[i] = __float2bfloat16(v);
}

// ---------------- input projection (SMEM-staged): h = x @ ipw^T + ipb ---------
__global__ void __launch_bounds__(256) input_proj_kernel(
    const float* __restrict__ t0, const float* __restrict__ t1,
    const float* __restrict__ t2, const float* __restrict__ t3,
    const float* __restrict__ ipw, const float* __restrict__ ipb)
{
    __shared__ float Ws[D_][IN_ + 1];
    __shared__ float xs[32][IN_ + 1];

    int blk = blockIdx.x;                 // 0..511
    int s   = blk >> 7;
    int bt0 = (blk * 32) & 4095;
    const float* x = (s == 0) ? t0 : (s == 1) ? t1 : (s == 2) ? t2 : t3;

    const float* wsrc = ipw + (long)s * D_ * IN_;
    for (int i = threadIdx.x; i < D_ * IN_; i += 256)
        Ws[i >> 5][i & 31] = wsrc[i];
    const float* xsrc = x + (long)bt0 * IN_;
    for (int i = threadIdx.x; i < 32 * IN_; i += 256)
        xs[i >> 5][i & 31] = xsrc[i];
    __syncthreads();

    int d = threadIdx.x;
    float w[IN_];
#pragma unroll
    for (int k = 0; k < IN_; ++k) w[k] = Ws[d][k];
    float bias = ipb[s * D_ + d];

    long gbase = (long)blk * 32 * D_ + d;
#pragma unroll 4
    for (int r = 0; r < 32; ++r) {
        float acc = bias;
#pragma unroll
        for (int k = 0; k < IN_; ++k) acc = fmaf(xs[r][k], w[k], acc);
        long o = gbase + (long)r * D_;
        g_h[o] = acc;
        g_h_bf[o] = __float2bfloat16(acc);
    }
}

// ---------------- HMMA bf16 GEMM (single term, templated BM/BN) ---------------
// C[M,N] = A[M,K] * W[N,K]^T, bf16 inputs, fp32 accum.
// CTA tile BMxBNx32, 8 warps: WM = BM/32 m-warps x WN = 8/WM n-warps.
// Warp tile 32 x (BN/WN), mma m16n8k16 via ldmatrix.x4.
#define RPAD 80            // bytes per SMEM row (40 bf16)

template<int BM, int BN>
__global__ void __launch_bounds__(256) gemm_tc_kernel(
    const bf16* __restrict__ Abf, long aStride,
    const bf16* __restrict__ Wbf, long wStride,
    float* __restrict__ C, int ldc, long cStride,
    bf16* __restrict__ Cbf,
    int K, int nValid)
{
    constexpr int WM    = BM / 32;                // m-warps (4 or 2)
    constexpr int WN    = 8 / WM;                 // n-warps
    constexpr int WCOLS = BN / WN;                // cols per warp
    constexpr int NI    = WCOLS / 8;              // 8-col tiles per warp
    constexpr int STG_B = (BM + BN) * RPAD;       // bytes per stage
    constexpr int W_OFF = BM * RPAD;
    constexpr int NCP   = (BM + BN) * 4;          // cp16 ops per stage

    extern __shared__ char smem[];
    uint32_t sb = smem_u32(smem);
    int tid = threadIdx.x;
    int wid = tid >> 5, lid = tid & 31;
    int warp_m = wid & (WM - 1), warp_n = wid / WM;
    int gid = lid >> 2, ktid = lid & 3;
    int s = blockIdx.z;
    long bm = (long)blockIdx.y * BM;
    long bn = (long)blockIdx.x * BN;

    const bf16* A = Abf + s * aStride;
    const bf16* W = Wbf + s * wStride;

    float acc[2][NI][4];
#pragma unroll
    for (int mi = 0; mi < 2; ++mi)
#pragma unroll
        for (int ni = 0; ni < NI; ++ni)
#pragma unroll
            for (int q = 0; q < 4; ++q) acc[mi][ni][q] = 0.f;

    auto load_stage = [&](int stg, int k0) {
        uint32_t base = sb + stg * STG_B;
#pragma unroll
        for (int i = tid; i < NCP; i += 256) {
            const bf16* src; uint32_t doff;
            if (i < BM * 4) {
                int r = i >> 2, c = i & 3;
                src  = A + (bm + r) * K + k0 + c * 8;
                doff = base + r * RPAD + c * 16;
            } else {
                int j = i - BM * 4, r = j >> 2, c = j & 3;
                src  = W + (bn + r) * K + k0 + c * 8;
                doff = base + W_OFF + r * RPAD + c * 16;
            }
            cp16(doff, src);
        }
    };

    int nst = K >> 5;
    load_stage(0, 0);
    CP_COMMIT();

    uint32_t aoff = (uint32_t)(warp_m * 32 + (lid & 7) + ((lid >> 3) & 1) * 8) * RPAD
                  + ((lid >> 4) & 1) * 16;
    uint32_t boff = (uint32_t)(warp_n * WCOLS + ((lid >> 4) & 1) * 8 + (lid & 7)) * RPAD
                  + ((lid >> 3) & 1) * 16;

    for (int st = 0; st < nst; ++st) {
        if (st + 1 < nst) {
            load_stage((st + 1) & 1, (st + 1) << 5);
            CP_COMMIT();
            CP_WAIT1();
        } else {
            CP_WAIT0();
        }
        __syncthreads();

        uint32_t stg = sb + (st & 1) * STG_B;

#pragma unroll
        for (int kc = 0; kc < 2; ++kc) {
            int kb = kc * 32;
            uint32_t ah[2][4], bh[NI][2], t4[4];
#pragma unroll
            for (int mi = 0; mi < 2; ++mi)
                ldsm_x4(ah[mi], stg + aoff + mi * 16 * RPAD + kb);
#pragma unroll
            for (int pr = 0; pr < NI / 2; ++pr) {
                ldsm_x4(t4, stg + W_OFF + boff + pr * 16 * RPAD + kb);
                bh[2 * pr][0] = t4[0]; bh[2 * pr][1] = t4[1];
                bh[2 * pr + 1][0] = t4[2]; bh[2 * pr + 1][1] = t4[3];
            }
#pragma unroll
            for (int mi = 0; mi < 2; ++mi)
#pragma unroll
                for (int ni = 0; ni < NI; ++ni)
                    mma_bf16(acc[mi][ni], ah[mi], bh[ni]);
        }
        __syncthreads();
    }

#pragma unroll
    for (int mi = 0; mi < 2; ++mi) {
        long row = bm + warp_m * 32 + mi * 16 + gid;
#pragma unroll
        for (int ni = 0; ni < NI; ++ni) {
            int cl = warp_n * WCOLS + ni * 8 + ktid * 2;
            if (cl >= nValid) continue;
            float* c0 = C + s * cStride + row * ldc + bn + cl;
            float* c1 = C + s * cStride + (row + 8) * ldc + bn + cl;
            *(float2*)c0 = make_float2(acc[mi][ni][0], acc[mi][ni][1]);
            *(float2*)c1 = make_float2(acc[mi][ni][2], acc[mi][ni][3]);
            if (Cbf) {
                __nv_bfloat162 hv;
                hv.x = __float2bfloat16(acc[mi][ni][0]);
                hv.y = __float2bfloat16(acc[mi][ni][1]);
                *(__nv_bfloat162*)(Cbf + s * cStride + row * ldc + bn + cl) = hv;
                hv.x = __float2bfloat16(acc[mi][ni][2]);
                hv.y = __float2bfloat16(acc[mi][ni][3]);
                *(__nv_bfloat162*)(Cbf + s * cStride + (row + 8) * ldc + bn + cl) = hv;
            }
        }
    }
}

#define GSM_128_128 (2 * (128 + 128) * RPAD)   // 40960
#define GSM_128_64  (2 * (128 + 64) * RPAD)    // 30720
#define GSM_64_64   (2 * (64 + 64) * RPAD)     // 20480

// ---------------- depthwise causal conv (K=4) + bias + silu -------------------
__global__ void __launch_bounds__(128) conv_silu_kernel(
    const float* __restrict__ cw, const float* __restrict__ cb, int l)
{
    int zidx = blockIdx.z;                // 0..31  (s*8+b)
    int s = zidx >> 3, b = zidx & 7;
    int c = blockIdx.y;                   // 0..7 t-chunk
    int t0 = c * 64;
    int d = blockIdx.x * 128 + threadIdx.x;
    int sl = s * L_ + l;

    const float* w = cw + ((long)sl * DI_ + d) * KC_;
    float w0 = w[0], w1 = w[1], w2 = w[2], w3 = w[3];
    float bias = cb[sl * DI_ + d];

    long rowbase = (long)s * ROWS + (long)b * T_;
    const float* xi = g_xz + (rowbase + t0) * 2 * DI_ + d;
    long ub = (rowbase + t0) * DI_ + d;

    float x0, x1, x2;
    if (t0) {
        x0 = xi[-3 * 2 * DI_]; x1 = xi[-2 * 2 * DI_]; x2 = xi[-1 * 2 * DI_];
    } else {
        x0 = x1 = x2 = 0.f;
    }
#pragma unroll 4
    for (int tt = 0; tt < 64; ++tt) {
        float x3 = xi[(long)tt * 2 * DI_];
        float a = fmaf(w0, x0, fmaf(w1, x1, fmaf(w2, x2, fmaf(w3, x3, bias))));
        float uv = silu_f(a);
        long o = ub + (long)tt * DI_;
        g_u[o] = uv;
        g_u_bf[o] = __float2bfloat16(uv);
        x0 = x1; x1 = x2; x2 = x3;
    }
}

// ---------------- fused dt + SSM scan + skip + gate (R14 known-good) ----------
#define SCH 16
__global__ void __launch_bounds__(64) scan_kernel(
    const float* __restrict__ dtw, const float* __restrict__ dtb,
    const float* __restrict__ alog, const float* __restrict__ dpar, int l)
{
    __shared__ float s_xd[SCH * 48];
    __shared__ float s_u[SCH][64];
    __shared__ float s_z[SCH][64];

    int s = blockIdx.z, b = blockIdx.y;
    int d = blockIdx.x * 64 + threadIdx.x;
    int sl = s * L_ + l;

    float A[N_];
    const float* ap = alog + ((long)sl * DI_ + d) * N_;
#pragma unroll
    for (int n = 0; n < N_; ++n) A[n] = -__expf(ap[n]);
    float A0 = A[0];
    bool geo = true;
#pragma unroll
    for (int n = 1; n < N_; ++n)
        geo = geo && (fabsf(A[n] - (float)(n + 1) * A0) <= 1e-4f * fabsf(A[n]) + 1e-6f);

    float wdt[R_];
    const float* wp = dtw + ((long)sl * DI_ + d) * R_;
#pragma unroll
    for (int r = 0; r < R_; ++r) wdt[r] = wp[r];

    float dtbias = dtb[sl * DI_ + d];
    float Dp     = dpar[sl * DI_ + d];

    long rowbase = (long)s * ROWS + (long)b * T_;
    const float* up = g_u  + rowbase * DI_ + d;
    const float* zp = g_xz + rowbase * 2 * DI_ + DI_ + d;
    const float* xd = g_xdbl + rowbase * 48;
    long yb = rowbase * DI_ + d;

    float h[N_];
#pragma unroll
    for (int n = 0; n < N_; ++n) h[n] = 0.f;

    for (int t0 = 0; t0 < T_; t0 += SCH) {
        __syncthreads();
        const float4* src = (const float4*)(xd + (long)t0 * 48);
        for (int i = threadIdx.x; i < SCH * 12; i += 64)
            ((float4*)s_xd)[i] = src[i];
#pragma unroll
        for (int tt = 0; tt < SCH; ++tt) {
            s_u[tt][threadIdx.x] = up[(long)(t0 + tt) * DI_];
            s_z[tt][threadIdx.x] = zp[(long)(t0 + tt) * 2 * DI_];
        }
        __syncthreads();

#pragma unroll 2
        for (int tt = 0; tt < SCH; ++tt) {
            const float4* q = (const float4*)(s_xd + tt * 48);
            float xr[48];
#pragma unroll
            for (int i = 0; i < 12; ++i) {
                float4 v = q[i];
                xr[i * 4 + 0] = v.x; xr[i * 4 + 1] = v.y;
                xr[i * 4 + 2] = v.z; xr[i * 4 + 3] = v.w;
            }
            float a0 = dtbias, a1 = 0.f, a2 = 0.f, a3 = 0.f;
#pragma unroll
            for (int r = 0; r < 4; ++r) {
                a0 = fmaf(xr[r],      wdt[r],      a0);
                a1 = fmaf(xr[r + 4],  wdt[r + 4],  a1);
                a2 = fmaf(xr[r + 8],  wdt[r + 8],  a2);
                a3 = fmaf(xr[r + 12], wdt[r + 12], a3);
            }
            float dt = softplus_f((a0 + a1) + (a2 + a3));

            float u = s_u[tt][threadIdx.x];
            float z = s_z[tt][threadIdx.x];
            float du = dt * u;

            float y0 = 0.f, y1 = 0.f, y2 = 0.f, y3 = 0.f;
            if (geo) {
                float p = __expf(dt * A0);
                float p2 = p * p, p4 = p2 * p2, p8 = p4 * p4;
                float pw[16];
                pw[0] = p;       pw[1] = p2;       pw[2] = p2 * p;   pw[3] = p4;
                pw[4] = p4 * p;  pw[5] = p4 * p2;  pw[6] = p4 * pw[2]; pw[7] = p8;
                pw[8] = p8 * p;  pw[9] = p8 * p2;  pw[10] = p8 * pw[2]; pw[11] = p8 * p4;
                pw[12] = p8 * pw[4]; pw[13] = p8 * pw[5]; pw[14] = p8 * pw[6]; pw[15] = p8 * p8;
#pragma unroll
                for (int n = 0; n < N_; ++n)
                    h[n] = fmaf(pw[n], h[n], du * xr[16 + n]);
            } else {
#pragma unroll
                for (int n = 0; n < N_; ++n) {
                    float dA = __expf(dt * A[n]);
                    h[n] = fmaf(dA, h[n], du * xr[16 + n]);
                }
            }
#pragma unroll
            for (int n = 0; n < N_; n += 4) {
                y0 = fmaf(h[n],     xr[32 + n],     y0);
                y1 = fmaf(h[n + 1], xr[33 + n],     y1);
                y2 = fmaf(h[n + 2], xr[34 + n],     y2);
                y3 = fmaf(h[n + 3], xr[35 + n],     y3);
            }
            float y = ((y0 + y1) + (y2 + y3) + u * Dp) * silu_f(z);
            g_y_bf[yb + (long)(t0 + tt) * DI_] = __float2bfloat16(y);
        }
    }
}

// ---------------- mean over t (two-stage) + output projection -----------------
__global__ void __launch_bounds__(256) mean_part_kernel()
{
    int c = blockIdx.x, b = blockIdx.y, s = blockIdx.z;
    int d = threadIdx.x;
    const float* hp = g_h + ((long)s * ROWS + (long)b * T_ + (long)c * 64) * D_ + d;
    float acc = 0.f;
#pragma unroll 8
    for (int t = 0; t < 64; ++t) acc += hp[(long)t * D_];
    g_hpart[(((long)s * B_ + b) * 8 + c) * D_ + d] = acc;
}

__global__ void __launch_bounds__(256) meanout_kernel(
    const float* __restrict__ opw, const float* __restrict__ opb, float* __restrict__ out)
{
    int b = blockIdx.x, s = blockIdx.y;
    __shared__ float hm[D_];
    int d = threadIdx.x;
    const float* pp = g_hpart + ((long)s * B_ + b) * 8 * D_ + d;
    float acc = 0.f;
#pragma unroll
    for (int c = 0; c < 8; ++c) acc += pp[(long)c * D_];
    hm[d] = acc * (1.f / T_);
    __syncthreads();

    if (d < E_) {
        const float* w = opw + ((long)s * E_ + d) * D_;
        float e = opb[s * E_ + d];
#pragma unroll 8
        for (int k = 0; k < D_; ++k) e = fmaf(hm[k], w[k], e);
        out[((long)s * B_ + b) * E_ + d] = e;
    }
}

__global__ void combine_kernel(float* __restrict__ out)
{
    int i = blockIdx.x * blockDim.x + threadIdx.x;
    if (i < B_ * E_)
        out[4 * B_ * E_ + i] = out[i] + out[B_ * E_ + i] + out[2 * B_ * E_ + i] + out[3 * B_ * E_ + i];
}

// ---------------- launcher ----------------------------------------------------
extern "C" void kernel_launch(void* const* d_in, const int* in_sizes, int n_in,
                              void* d_out, int out_size)
{
    const float* trend    = (const float*)d_in[0];
    const float* daily    = (const float*)d_in[1];
    const float* weekly   = (const float*)d_in[2];
    const float* residual = (const float*)d_in[3];
    const float* in_proj_w  = (const float*)d_in[4];
    const float* conv_w     = (const float*)d_in[5];
    const float* conv_b     = (const float*)d_in[6];
    const float* x_proj_w   = (const float*)d_in[7];
    const float* dt_proj_w  = (const float*)d_in[8];
    const float* dt_proj_b  = (const float*)d_in[9];
    const float* A_log      = (const float*)d_in[10];
    const float* D_param    = (const float*)d_in[11];
    const float* out_proj_w = (const float*)d_in[12];
    const float* input_proj_w  = (const float*)d_in[13];
    const float* input_proj_b  = (const float*)d_in[14];
    const float* output_proj_w = (const float*)d_in[15];
    const float* output_proj_b = (const float*)d_in[16];
    float* out = (float*)d_out;

    cudaFuncSetAttribute((const void*)gemm_tc_kernel<128, 128>,
                         cudaFuncAttributeMaxDynamicSharedMemorySize, GSM_128_128);
    cudaFuncSetAttribute((const void*)gemm_tc_kernel<128, 64>,
                         cudaFuncAttributeMaxDynamicSharedMemorySize, GSM_128_64);
    cudaFuncSetAttribute((const void*)gemm_tc_kernel<64, 64>,
                         cudaFuncAttributeMaxDynamicSharedMemorySize, GSM_64_64);

    bf16 *inw_bf, *outw_bf, *xpw_bf, *h_bf, *u_bf, *y_bf;
    float *xz, *xdbl, *hbuf;
    cudaGetSymbolAddress((void**)&inw_bf,  g_inw_bf);
    cudaGetSymbolAddress((void**)&outw_bf, g_outw_bf);
    cudaGetSymbolAddress((void**)&xpw_bf,  g_xpw_bf);
    cudaGetSymbolAddress((void**)&h_bf,    g_h_bf);
    cudaGetSymbolAddress((void**)&u_bf,    g_u_bf);
    cudaGetSymbolAddress((void**)&y_bf,    g_y_bf);
    cudaGetSymbolAddress((void**)&xz,      g_xz);
    cudaGetSymbolAddress((void**)&xdbl,    g_xdbl);
    cudaGetSymbolAddress((void**)&hbuf,    g_h);

    // Launch order keeps the big in_proj GEMM at stream-launch index 3
    // (the launch ncu captures).
    {
        int n1 = S_ * L_ * 2 * DI_ * D_;                               // (0)
        convert_bf_kernel<<<(n1 + 255) / 256, 256>>>(in_proj_w, inw_bf, n1);
    }
    input_proj_kernel<<<TROWS / 32, 256>>>(trend, daily, weekly, residual,
                                           input_proj_w, input_proj_b);  // (1)
    {
        int n2 = S_ * L_ * D_ * DI_;                                   // (2)
        convert_bf_kernel<<<(n2 + 255) / 256, 256>>>(out_proj_w, outw_bf, n2);
    }

    bool xpw_converted = false;
    for (int l = 0; l < L_; ++l) {
        {
            dim3 g(2 * DI_ / 128, 32, S_);                             // (3) <- profiled
            gemm_tc_kernel<128, 128><<<g, 256, GSM_128_128>>>(
                h_bf, (long)ROWS * D_,
                inw_bf + (long)l * 2 * DI_ * D_, (long)L_ * 2 * DI_ * D_,
                xz, 2 * DI_, (long)ROWS * 2 * DI_,
                nullptr, D_, 128);
        }
        if (!xpw_converted) {
            int n3 = S_ * L_ * 64 * DI_;                               // (4)
            convert_xpw_kernel<<<(n3 + 255) / 256, 256>>>(x_proj_w);
            xpw_converted = true;
        }
        {
            dim3 g(DI_ / 128, 8, 32);                                  // t-parallel conv
            conv_silu_kernel<<<g, 128>>>(conv_w, conv_b, l);
        }
        {
            dim3 g(1, 64, S_);                                         // BM=64: 256 CTAs
            gemm_tc_kernel<64, 64><<<g, 256, GSM_64_64>>>(
                u_bf, (long)ROWS * DI_,
                xpw_bf + (long)l * 64 * DI_, (long)L_ * 64 * DI_,
                xdbl, 48, (long)ROWS * 48,
                nullptr, DI_, 48);
        }
        {
            dim3 g(DI_ / 64, B_, S_);
            scan_kernel<<<g, 64>>>(dt_proj_w, dt_proj_b, A_log, D_param, l);
        }
        {
            dim3 g(D_ / 64, 32, S_);                                   // R14 config
            gemm_tc_kernel<128, 64><<<g, 256, GSM_128_64>>>(
                y_bf, (long)ROWS * DI_,
                outw_bf + (long)l * D_ * DI_, (long)L_ * D_ * DI_,
                hbuf, D_, (long)ROWS * D_,
                h_bf, DI_, 64);
        }
    }

    {
        dim3 gp(8, B_, S_);
        mean_part_kernel<<<gp, 256>>>();
    }
    dim3 g_mo(B_, S_);
    meanout_kernel<<<g_mo, 256>>>(output_proj_w, output_proj_b, out);
    combine_kernel<<<4, 256>>>(out);
}

// round 17
// speedup vs baseline: 1.1869x; 1.0083x over previous
#include <cuda_runtime.h>
#include <cuda_bf16.h>
#include <cstdint>
#include <math.h>

#define S_  4
#define L_  3
#define D_  256
#define DI_ 512
#define N_  16
#define KC_ 4
#define R_  16
#define IN_ 32
#define E_  128
#define B_  8
#define T_  512
#define ROWS  (B_*T_)      // 4096 rows per stream
#define TROWS (S_*ROWS)    // 16384 total rows

typedef __nv_bfloat16 bf16;

// ---------------- scratch (device globals; no runtime allocation) ------------
__device__ float g_h   [S_*ROWS*D_];
__device__ float g_xz  [S_*ROWS*2*DI_];     // xi = [:,0:512], z = [:,512:1024]
__device__ float g_u   [S_*ROWS*DI_];
__device__ float g_xdbl[S_*ROWS*48];        // dt_in[0:16], B[16:32], C[32:48]
__device__ float g_hpart[S_*B_*8*D_];

__device__ bf16 g_h_bf [S_*ROWS*D_];
__device__ bf16 g_u_bf [S_*ROWS*DI_];
__device__ bf16 g_y_bf [S_*ROWS*DI_];

__device__ bf16 g_inw_bf [S_*L_*2*DI_*D_];
__device__ bf16 g_outw_bf[S_*L_*D_*DI_];
__device__ bf16 g_xpw_bf [S_*L_*64*DI_];    // padded 48 -> 64 rows

// ---------------- helpers ----------------------------------------------------
__device__ __forceinline__ float softplus_f(float x) {
    float e = __expf(x);
    return (x > 20.f) ? x : __logf(1.f + e);
}
__device__ __forceinline__ float silu_f(float x) {
    return x / (1.f + __expf(-x));
}
__device__ __forceinline__ uint32_t smem_u32(const void* p) {
    uint32_t a;
    asm("{ .reg .u64 t; cvta.to.shared.u64 t, %1; cvt.u32.u64 %0, t; }" : "=r"(a) : "l"(p));
    return a;
}
__device__ __forceinline__ void cp16(uint32_t dst, const void* src) {
    asm volatile("cp.async.cg.shared.global [%0], [%1], 16;" :: "r"(dst), "l"(src));
}
#define CP_COMMIT() asm volatile("cp.async.commit_group;")
#define CP_WAIT0()  asm volatile("cp.async.wait_group 0;")
#define CP_WAIT1()  asm volatile("cp.async.wait_group 1;")

__device__ __forceinline__ void mma_bf16(float* c, const uint32_t* a, const uint32_t* b) {
    asm volatile(
        "mma.sync.aligned.m16n8k16.row.col.f32.bf16.bf16.f32 "
        "{%0,%1,%2,%3}, {%4,%5,%6,%7}, {%8,%9}, {%0,%1,%2,%3};"
        : "+f"(c[0]), "+f"(c[1]), "+f"(c[2]), "+f"(c[3])
        : "r"(a[0]), "r"(a[1]), "r"(a[2]), "r"(a[3]), "r"(b[0]), "r"(b[1]));
}
__device__ __forceinline__ void ldsm_x4(uint32_t* r, uint32_t addr) {
    asm volatile("ldmatrix.sync.aligned.m8n8.x4.shared.b16 {%0,%1,%2,%3}, [%4];"
        : "=r"(r[0]), "=r"(r[1]), "=r"(r[2]), "=r"(r[3]) : "r"(addr));
}

// ---------------- weight conversion ------------------------------------------
__global__ void convert_bf_kernel(const float* __restrict__ src,
                                  bf16* __restrict__ dst, int n)
{
    int i = blockIdx.x * blockDim.x + threadIdx.x;
    if (i < n) dst[i] = __float2bfloat16(src[i]);
}

__global__ void convert_xpw_kernel(const float* __restrict__ src)  // [S*L][48][512] -> padded 64
{
    int i = blockIdx.x * blockDim.x + threadIdx.x;
    int n = S_ * L_ * 64 * DI_;
    if (i >= n) return;
    int k = i % DI_;
    int row = (i / DI_) % 64;
    int sl = i / (64 * DI_);
    float v = (row < 48) ? src[((long)sl * 48 + row) * DI_ + k] : 0.f;
    g_xpw_bf[i] = __float2bfloat16(v);
}

// ---------------- input projection (SMEM-staged): h = x @ ipw^T + ipb ---------
__global__ void __launch_bounds__(256) input_proj_kernel(
    const float* __restrict__ t0, const float* __restrict__ t1,
    const float* __restrict__ t2, const float* __restrict__ t3,
    const float* __restrict__ ipw, const float* __restrict__ ipb)
{
    __shared__ float Ws[D_][IN_ + 1];
    __shared__ float xs[32][IN_ + 1];

    int blk = blockIdx.x;                 // 0..511
    int s   = blk >> 7;
    int bt0 = (blk * 32) & 4095;
    const float* x = (s == 0) ? t0 : (s == 1) ? t1 : (s == 2) ? t2 : t3;

    const float* wsrc = ipw + (long)s * D_ * IN_;
    for (int i = threadIdx.x; i < D_ * IN_; i += 256)
        Ws[i >> 5][i & 31] = wsrc[i];
    const float* xsrc = x + (long)bt0 * IN_;
    for (int i = threadIdx.x; i < 32 * IN_; i += 256)
        xs[i >> 5][i & 31] = xsrc[i];
    __syncthreads();

    int d = threadIdx.x;
    float w[IN_];
#pragma unroll
    for (int k = 0; k < IN_; ++k) w[k] = Ws[d][k];
    float bias = ipb[s * D_ + d];

    long gbase = (long)blk * 32 * D_ + d;
#pragma unroll 4
    for (int r = 0; r < 32; ++r) {
        float acc = bias;
#pragma unroll
        for (int k = 0; k < IN_; ++k) acc = fmaf(xs[r][k], w[k], acc);
        long o = gbase + (long)r * D_;
        g_h[o] = acc;
        g_h_bf[o] = __float2bfloat16(acc);
    }
}

// ---------------- HMMA bf16 GEMM (single term, templated BM/BN) ---------------
#define RPAD 80            // bytes per SMEM row (40 bf16)

template<int BM, int BN>
__global__ void __launch_bounds__(256) gemm_tc_kernel(
    const bf16* __restrict__ Abf, long aStride,
    const bf16* __restrict__ Wbf, long wStride,
    float* __restrict__ C, int ldc, long cStride,
    bf16* __restrict__ Cbf,
    int K, int nValid)
{
    constexpr int WM    = BM / 32;
    constexpr int WN    = 8 / WM;
    constexpr int WCOLS = BN / WN;
    constexpr int NI    = WCOLS / 8;
    constexpr int STG_B = (BM + BN) * RPAD;
    constexpr int W_OFF = BM * RPAD;
    constexpr int NCP   = (BM + BN) * 4;

    extern __shared__ char smem[];
    uint32_t sb = smem_u32(smem);
    int tid = threadIdx.x;
    int wid = tid >> 5, lid = tid & 31;
    int warp_m = wid & (WM - 1), warp_n = wid / WM;
    int gid = lid >> 2, ktid = lid & 3;
    int s = blockIdx.z;
    long bm = (long)blockIdx.y * BM;
    long bn = (long)blockIdx.x * BN;

    const bf16* A = Abf + s * aStride;
    const bf16* W = Wbf + s * wStride;

    float acc[2][NI][4];
#pragma unroll
    for (int mi = 0; mi < 2; ++mi)
#pragma unroll
        for (int ni = 0; ni < NI; ++ni)
#pragma unroll
            for (int q = 0; q < 4; ++q) acc[mi][ni][q] = 0.f;

    auto load_stage = [&](int stg, int k0) {
        uint32_t base = sb + stg * STG_B;
#pragma unroll
        for (int i = tid; i < NCP; i += 256) {
            const bf16* src; uint32_t doff;
            if (i < BM * 4) {
                int r = i >> 2, c = i & 3;
                src  = A + (bm + r) * K + k0 + c * 8;
                doff = base + r * RPAD + c * 16;
            } else {
                int j = i - BM * 4, r = j >> 2, c = j & 3;
                src  = W + (bn + r) * K + k0 + c * 8;
                doff = base + W_OFF + r * RPAD + c * 16;
            }
            cp16(doff, src);
        }
    };

    int nst = K >> 5;
    load_stage(0, 0);
    CP_COMMIT();

    uint32_t aoff = (uint32_t)(warp_m * 32 + (lid & 7) + ((lid >> 3) & 1) * 8) * RPAD
                  + ((lid >> 4) & 1) * 16;
    uint32_t boff = (uint32_t)(warp_n * WCOLS + ((lid >> 4) & 1) * 8 + (lid & 7)) * RPAD
                  + ((lid >> 3) & 1) * 16;

    for (int st = 0; st < nst; ++st) {
        if (st + 1 < nst) {
            load_stage((st + 1) & 1, (st + 1) << 5);
            CP_COMMIT();
            CP_WAIT1();
        } else {
            CP_WAIT0();
        }
        __syncthreads();

        uint32_t stg = sb + (st & 1) * STG_B;

#pragma unroll
        for (int kc = 0; kc < 2; ++kc) {
            int kb = kc * 32;
            uint32_t ah[2][4], bh[NI][2], t4[4];
#pragma unroll
            for (int mi = 0; mi < 2; ++mi)
                ldsm_x4(ah[mi], stg + aoff + mi * 16 * RPAD + kb);
#pragma unroll
            for (int pr = 0; pr < NI / 2; ++pr) {
                ldsm_x4(t4, stg + W_OFF + boff + pr * 16 * RPAD + kb);
                bh[2 * pr][0] = t4[0]; bh[2 * pr][1] = t4[1];
                bh[2 * pr + 1][0] = t4[2]; bh[2 * pr + 1][1] = t4[3];
            }
#pragma unroll
            for (int mi = 0; mi < 2; ++mi)
#pragma unroll
                for (int ni = 0; ni < NI; ++ni)
                    mma_bf16(acc[mi][ni], ah[mi], bh[ni]);
        }
        __syncthreads();
    }

#pragma unroll
    for (int mi = 0; mi < 2; ++mi) {
        long row = bm + warp_m * 32 + mi * 16 + gid;
#pragma unroll
        for (int ni = 0; ni < NI; ++ni) {
            int cl = warp_n * WCOLS + ni * 8 + ktid * 2;
            if (cl >= nValid) continue;
            float* c0 = C + s * cStride + row * ldc + bn + cl;
            float* c1 = C + s * cStride + (row + 8) * ldc + bn + cl;
            *(float2*)c0 = make_float2(acc[mi][ni][0], acc[mi][ni][1]);
            *(float2*)c1 = make_float2(acc[mi][ni][2], acc[mi][ni][3]);
            if (Cbf) {
                __nv_bfloat162 hv;
                hv.x = __float2bfloat16(acc[mi][ni][0]);
                hv.y = __float2bfloat16(acc[mi][ni][1]);
                *(__nv_bfloat162*)(Cbf + s * cStride + row * ldc + bn + cl) = hv;
                hv.x = __float2bfloat16(acc[mi][ni][2]);
                hv.y = __float2bfloat16(acc[mi][ni][3]);
                *(__nv_bfloat162*)(Cbf + s * cStride + (row + 8) * ldc + bn + cl) = hv;
            }
        }
    }
}

#define GSM_128_128 (2 * (128 + 128) * RPAD)   // 40960
#define GSM_128_64  (2 * (128 + 64) * RPAD)    // 30720
#define GSM_64_64   (2 * (64 + 64) * RPAD)     // 20480

// ---------------- depthwise causal conv (K=4) + bias + silu -------------------
__global__ void __launch_bounds__(128) conv_silu_kernel(
    const float* __restrict__ cw, const float* __restrict__ cb, int l)
{
    int zidx = blockIdx.z;                // 0..31  (s*8+b)
    int s = zidx >> 3, b = zidx & 7;
    int c = blockIdx.y;                   // 0..7 t-chunk
    int t0 = c * 64;
    int d = blockIdx.x * 128 + threadIdx.x;
    int sl = s * L_ + l;

    const float* w = cw + ((long)sl * DI_ + d) * KC_;
    float w0 = w[0], w1 = w[1], w2 = w[2], w3 = w[3];
    float bias = cb[sl * DI_ + d];

    long rowbase = (long)s * ROWS + (long)b * T_;
    const float* xi = g_xz + (rowbase + t0) * 2 * DI_ + d;
    long ub = (rowbase + t0) * DI_ + d;

    float x0, x1, x2;
    if (t0) {
        x0 = xi[-3 * 2 * DI_]; x1 = xi[-2 * 2 * DI_]; x2 = xi[-1 * 2 * DI_];
    } else {
        x0 = x1 = x2 = 0.f;
    }
#pragma unroll 4
    for (int tt = 0; tt < 64; ++tt) {
        float x3 = xi[(long)tt * 2 * DI_];
        float a = fmaf(w0, x0, fmaf(w1, x1, fmaf(w2, x2, fmaf(w3, x3, bias))));
        float uv = silu_f(a);
        long o = ub + (long)tt * DI_;
        g_u[o] = uv;
        g_u_bf[o] = __float2bfloat16(uv);
        x0 = x1; x1 = x2; x2 = x3;
    }
}

// ---------------- fused dt + SSM scan + skip + gate ---------------------------
// Two-phase chunks: Phase A hoists ALL transcendental work (softplus/exp/silu)
// out of the recurrence into 16 independent chains; Phase B runs the serial
// h-recurrence with only FMA/MUL on the carried path.
#define SCH 16
__global__ void __launch_bounds__(64) scan_kernel(
    const float* __restrict__ dtw, const float* __restrict__ dtb,
    const float* __restrict__ alog, const float* __restrict__ dpar, int l)
{
    __shared__ float s_xd[SCH * 48];
    __shared__ float s_u[SCH][64];
    __shared__ float s_z[SCH][64];

    int s = blockIdx.z, b = blockIdx.y;
    int d = blockIdx.x * 64 + threadIdx.x;
    int sl = s * L_ + l;

    float A[N_];
    const float* ap = alog + ((long)sl * DI_ + d) * N_;
#pragma unroll
    for (int n = 0; n < N_; ++n) A[n] = -__expf(ap[n]);
    float A0 = A[0];
    bool geo = true;
#pragma unroll
    for (int n = 1; n < N_; ++n)
        geo = geo && (fabsf(A[n] - (float)(n + 1) * A0) <= 1e-4f * fabsf(A[n]) + 1e-6f);

    float wdt[R_];
    const float* wp = dtw + ((long)sl * DI_ + d) * R_;
#pragma unroll
    for (int r = 0; r < R_; ++r) wdt[r] = wp[r];

    float dtbias = dtb[sl * DI_ + d];
    float Dp     = dpar[sl * DI_ + d];

    long rowbase = (long)s * ROWS + (long)b * T_;
    const float* up = g_u  + rowbase * DI_ + d;
    const float* zp = g_xz + rowbase * 2 * DI_ + DI_ + d;
    const float* xd = g_xdbl + rowbase * 48;
    long yb = rowbase * DI_ + d;

    float h[N_];
#pragma unroll
    for (int n = 0; n < N_; ++n) h[n] = 0.f;

    for (int t0 = 0; t0 < T_; t0 += SCH) {
        __syncthreads();
        const float4* src = (const float4*)(xd + (long)t0 * 48);
        for (int i = threadIdx.x; i < SCH * 12; i += 64)
            ((float4*)s_xd)[i] = src[i];
#pragma unroll
        for (int tt = 0; tt < SCH; ++tt) {
            s_u[tt][threadIdx.x] = up[(long)(t0 + tt) * DI_];
            s_z[tt][threadIdx.x] = zp[(long)(t0 + tt) * 2 * DI_];
        }
        __syncthreads();

        if (geo) {
            // ---- Phase A: all data-parallel transcendental work, 16 chains
            float pA[SCH], duA[SCH], c1A[SCH], c2A[SCH];
#pragma unroll
            for (int tt = 0; tt < SCH; ++tt) {
                const float* row = s_xd + tt * 48;
                float4 q0 = ((const float4*)row)[0];
                float4 q1 = ((const float4*)row)[1];
                float4 q2 = ((const float4*)row)[2];
                float4 q3 = ((const float4*)row)[3];
                float a0 = fmaf(q0.x, wdt[0], dtbias);
                float a1 = q1.x * wdt[4];
                float a2 = q2.x * wdt[8];
                float a3 = q3.x * wdt[12];
                a0 = fmaf(q0.y, wdt[1], a0); a1 = fmaf(q1.y, wdt[5], a1);
                a2 = fmaf(q2.y, wdt[9], a2); a3 = fmaf(q3.y, wdt[13], a3);
                a0 = fmaf(q0.z, wdt[2], a0); a1 = fmaf(q1.z, wdt[6], a1);
                a2 = fmaf(q2.z, wdt[10], a2); a3 = fmaf(q3.z, wdt[14], a3);
                a0 = fmaf(q0.w, wdt[3], a0); a1 = fmaf(q1.w, wdt[7], a1);
                a2 = fmaf(q2.w, wdt[11], a2); a3 = fmaf(q3.w, wdt[15], a3);
                float dt = softplus_f((a0 + a1) + (a2 + a3));

                float u = s_u[tt][threadIdx.x];
                float z = s_z[tt][threadIdx.x];
                float gz = silu_f(z);
                pA[tt]  = __expf(dt * A0);
                duA[tt] = dt * u;
                c1A[tt] = gz;
                c2A[tt] = u * Dp * gz;
            }
            // ---- Phase B: serial recurrence, FMA/MUL only on carried path
#pragma unroll 2
            for (int tt = 0; tt < SCH; ++tt) {
                const float* row = s_xd + tt * 48;
                float p = pA[tt];
                float p2 = p * p, p4 = p2 * p2, p8 = p4 * p4;
                float pw[16];
                pw[0] = p;        pw[1] = p2;       pw[2] = p2 * p;    pw[3] = p4;
                pw[4] = p4 * p;   pw[5] = p4 * p2;  pw[6] = p4 * pw[2]; pw[7] = p8;
                pw[8] = p8 * p;   pw[9] = p8 * p2;  pw[10] = p8 * pw[2]; pw[11] = p8 * p4;
                pw[12] = p8 * pw[4]; pw[13] = p8 * pw[5]; pw[14] = p8 * pw[6]; pw[15] = p8 * p8;
                float du = duA[tt];

                float xb[16], xc[16];
#pragma unroll
                for (int i = 0; i < 4; ++i) {
                    float4 v = ((const float4*)(row + 16))[i];
                    xb[i * 4] = v.x; xb[i * 4 + 1] = v.y; xb[i * 4 + 2] = v.z; xb[i * 4 + 3] = v.w;
                    float4 w4 = ((const float4*)(row + 32))[i];
                    xc[i * 4] = w4.x; xc[i * 4 + 1] = w4.y; xc[i * 4 + 2] = w4.z; xc[i * 4 + 3] = w4.w;
                }
                float y0 = 0.f, y1 = 0.f, y2 = 0.f, y3 = 0.f;
#pragma unroll
                for (int n = 0; n < N_; ++n)
                    h[n] = fmaf(pw[n], h[n], du * xb[n]);
#pragma unroll
                for (int n = 0; n < N_; n += 4) {
                    y0 = fmaf(h[n],     xc[n],     y0);
                    y1 = fmaf(h[n + 1], xc[n + 1], y1);
                    y2 = fmaf(h[n + 2], xc[n + 2], y2);
                    y3 = fmaf(h[n + 3], xc[n + 3], y3);
                }
                float y = fmaf(((y0 + y1) + (y2 + y3)), c1A[tt], c2A[tt]);
                g_y_bf[yb + (long)(t0 + tt) * DI_] = __float2bfloat16(y);
            }
        } else {
            // fallback: original fused loop (general A)
            for (int tt = 0; tt < SCH; ++tt) {
                const float4* q = (const float4*)(s_xd + tt * 48);
                float xr[48];
#pragma unroll
                for (int i = 0; i < 12; ++i) {
                    float4 v = q[i];
                    xr[i * 4 + 0] = v.x; xr[i * 4 + 1] = v.y;
                    xr[i * 4 + 2] = v.z; xr[i * 4 + 3] = v.w;
                }
                float a0 = dtbias, a1 = 0.f, a2 = 0.f, a3 = 0.f;
#pragma unroll
                for (int r = 0; r < 4; ++r) {
                    a0 = fmaf(xr[r],      wdt[r],      a0);
                    a1 = fmaf(xr[r + 4],  wdt[r + 4],  a1);
                    a2 = fmaf(xr[r + 8],  wdt[r + 8],  a2);
                    a3 = fmaf(xr[r + 12], wdt[r + 12], a3);
                }
                float dt = softplus_f((a0 + a1) + (a2 + a3));
                float u = s_u[tt][threadIdx.x];
                float z = s_z[tt][threadIdx.x];
                float du = dt * u;
                float y0 = 0.f, y1 = 0.f, y2 = 0.f, y3 = 0.f;
#pragma unroll
                for (int n = 0; n < N_; ++n) {
                    float dA = __expf(dt * A[n]);
                    h[n] = fmaf(dA, h[n], du * xr[16 + n]);
                }
#pragma unroll
                for (int n = 0; n < N_; n += 4) {
                    y0 = fmaf(h[n],     xr[32 + n], y0);
                    y1 = fmaf(h[n + 1], xr[33 + n], y1);
                    y2 = fmaf(h[n + 2], xr[34 + n], y2);
                    y3 = fmaf(h[n + 3], xr[35 + n], y3);
                }
                float y = ((y0 + y1) + (y2 + y3) + u * Dp) * silu_f(z);
                g_y_bf[yb + (long)(t0 + tt) * DI_] = __float2bfloat16(y);
            }
        }
    }
}

// ---------------- mean over t (two-stage) + output projection -----------------
__global__ void __launch_bounds__(256) mean_part_kernel()
{
    int c = blockIdx.x, b = blockIdx.y, s = blockIdx.z;
    int d = threadIdx.x;
    const float* hp = g_h + ((long)s * ROWS + (long)b * T_ + (long)c * 64) * D_ + d;
    float acc = 0.f;
#pragma unroll 8
    for (int t = 0; t < 64; ++t) acc += hp[(long)t * D_];
    g_hpart[(((long)s * B_ + b) * 8 + c) * D_ + d] = acc;
}

__global__ void __launch_bounds__(256) meanout_kernel(
    const float* __restrict__ opw, const float* __restrict__ opb, float* __restrict__ out)
{
    int b = blockIdx.x, s = blockIdx.y;
    __shared__ float hm[D_];
    int d = threadIdx.x;
    const float* pp = g_hpart + ((long)s * B_ + b) * 8 * D_ + d;
    float acc = 0.f;
#pragma unroll
    for (int c = 0; c < 8; ++c) acc += pp[(long)c * D_];
    hm[d] = acc * (1.f / T_);
    __syncthreads();

    if (d < E_) {
        const float* w = opw + ((long)s * E_ + d) * D_;
        float e = opb[s * E_ + d];
#pragma unroll 8
        for (int k = 0; k < D_; ++k) e = fmaf(hm[k], w[k], e);
        out[((long)s * B_ + b) * E_ + d] = e;
    }
}

__global__ void combine_kernel(float* __restrict__ out)
{
    int i = blockIdx.x * blockDim.x + threadIdx.x;
    if (i < B_ * E_)
        out[4 * B_ * E_ + i] = out[i] + out[B_ * E_ + i] + out[2 * B_ * E_ + i] + out[3 * B_ * E_ + i];
}

// ---------------- launcher ----------------------------------------------------
extern "C" void kernel_launch(void* const* d_in, const int* in_sizes, int n_in,
                              void* d_out, int out_size)
{
    const float* trend    = (const float*)d_in[0];
    const float* daily    = (const float*)d_in[1];
    const float* weekly   = (const float*)d_in[2];
    const float* residual = (const float*)d_in[3];
    const float* in_proj_w  = (const float*)d_in[4];
    const float* conv_w     = (const float*)d_in[5];
    const float* conv_b     = (const float*)d_in[6];
    const float* x_proj_w   = (const float*)d_in[7];
    const float* dt_proj_w  = (const float*)d_in[8];
    const float* dt_proj_b  = (const float*)d_in[9];
    const float* A_log      = (const float*)d_in[10];
    const float* D_param    = (const float*)d_in[11];
    const float* out_proj_w = (const float*)d_in[12];
    const float* input_proj_w  = (const float*)d_in[13];
    const float* input_proj_b  = (const float*)d_in[14];
    const float* output_proj_w = (const float*)d_in[15];
    const float* output_proj_b = (const float*)d_in[16];
    float* out = (float*)d_out;

    cudaFuncSetAttribute((const void*)gemm_tc_kernel<128, 128>,
                         cudaFuncAttributeMaxDynamicSharedMemorySize, GSM_128_128);
    cudaFuncSetAttribute((const void*)gemm_tc_kernel<128, 64>,
                         cudaFuncAttributeMaxDynamicSharedMemorySize, GSM_128_64);
    cudaFuncSetAttribute((const void*)gemm_tc_kernel<64, 64>,
                         cudaFuncAttributeMaxDynamicSharedMemorySize, GSM_64_64);

    bf16 *inw_bf, *outw_bf, *xpw_bf, *h_bf, *u_bf, *y_bf;
    float *xz, *xdbl, *hbuf;
    cudaGetSymbolAddress((void**)&inw_bf,  g_inw_bf);
    cudaGetSymbolAddress((void**)&outw_bf, g_outw_bf);
    cudaGetSymbolAddress((void**)&xpw_bf,  g_xpw_bf);
    cudaGetSymbolAddress((void**)&h_bf,    g_h_bf);
    cudaGetSymbolAddress((void**)&u_bf,    g_u_bf);
    cudaGetSymbolAddress((void**)&y_bf,    g_y_bf);
    cudaGetSymbolAddress((void**)&xz,      g_xz);
    cudaGetSymbolAddress((void**)&xdbl,    g_xdbl);
    cudaGetSymbolAddress((void**)&hbuf,    g_h);

    // Launch order keeps the big in_proj GEMM at stream-launch index 3
    // (the launch ncu captures) as a control metric.
    {
        int n1 = S_ * L_ * 2 * DI_ * D_;                               // (0)
        convert_bf_kernel<<<(n1 + 255) / 256, 256>>>(in_proj_w, inw_bf, n1);
    }
    input_proj_kernel<<<TROWS / 32, 256>>>(trend, daily, weekly, residual,
                                           input_proj_w, input_proj_b);  // (1)
    {
        int n2 = S_ * L_ * D_ * DI_;                                   // (2)
        convert_bf_kernel<<<(n2 + 255) / 256, 256>>>(out_proj_w, outw_bf, n2);
    }

    bool xpw_converted = false;
    for (int l = 0; l < L_; ++l) {
        {
            dim3 g(2 * DI_ / 128, 32, S_);                             // (3) <- profiled
            gemm_tc_kernel<128, 128><<<g, 256, GSM_128_128>>>(
                h_bf, (long)ROWS * D_,
                inw_bf + (long)l * 2 * DI_ * D_, (long)L_ * 2 * DI_ * D_,
                xz, 2 * DI_, (long)ROWS * 2 * DI_,
                nullptr, D_, 128);
        }
        if (!xpw_converted) {
            int n3 = S_ * L_ * 64 * DI_;                               // (4)
            convert_xpw_kernel<<<(n3 + 255) / 256, 256>>>(x_proj_w);
            xpw_converted = true;
        }
        {
            dim3 g(DI_ / 128, 8, 32);                                  // t-parallel conv
            conv_silu_kernel<<<g, 128>>>(conv_w, conv_b, l);
        }
        {
            dim3 g(1, 64, S_);                                         // BM=64: 256 CTAs
            gemm_tc_kernel<64, 64><<<g, 256, GSM_64_64>>>(
                u_bf, (long)ROWS * DI_,
                xpw_bf + (long)l * 64 * DI_, (long)L_ * 64 * DI_,
                xdbl, 48, (long)ROWS * 48,
                nullptr, DI_, 48);
        }
        {
            dim3 g(DI_ / 64, B_, S_);
            scan_kernel<<<g, 64>>>(dt_proj_w, dt_proj_b, A_log, D_param, l);
        }
        {
            dim3 g(D_ / 64, 32, S_);
            gemm_tc_kernel<128, 64><<<g, 256, GSM_128_64>>>(
                y_bf, (long)ROWS * DI_,
                outw_bf + (long)l * D_ * DI_, (long)L_ * D_ * DI_,
                hbuf, D_, (long)ROWS * D_,
                h_bf, DI_, 64);
        }
    }

    {
        dim3 gp(8, B_, S_);
        mean_part_kernel<<<gp, 256>>>();
    }
    dim3 g_mo(B_, S_);
    meanout_kernel<<<g_mo, 256>>>(output_proj_w, output_proj_b, out);
    combine_kernel<<<4, 256>>>(out);
}